// round 1
// baseline (speedup 1.0000x reference)
#include <cuda_runtime.h>
#include <cuda_bf16.h>

#define BB 4
#define CC 64
#define LL 4096
#define CQ 16
#define NH 4
#define NB 32
#define TJ 128
#define EPSV 1e-5f

// ---------------- scratch (device globals; no allocation at runtime) ----------------
__device__ float g_q[BB*LL*CQ];          // (b, l, cq)
__device__ float g_k[BB*LL*CQ];          // (b, l, cq)
__device__ float g_v[BB*LL*CC];          // (b, l, c)
__device__ int   g_sorted[BB*NH*LL];     // positions sorted by bucket (stable)
__device__ int   g_bstart[BB*NH*(NB+1)]; // bucket start offsets
__device__ float g_acc[NH*BB*LL*CC];     // per-hash attention output (b-major inside h)
__device__ float g_pre[BB*CC*LL];        // pre-batchnorm output
__device__ float g_stats[2*CC];          // per-channel sum / sumsq

// ---------------- K1: fused q/k/v 1x1 convs ----------------
__global__ void __launch_bounds__(128) k_qkv(const float* __restrict__ x,
    const float* __restrict__ Wq, const float* __restrict__ bq,
    const float* __restrict__ Wk, const float* __restrict__ bk,
    const float* __restrict__ Wv, const float* __restrict__ bv)
{
    __shared__ __align__(16) float sWq[CQ*CC];
    __shared__ __align__(16) float sWk[CQ*CC];
    __shared__ __align__(16) float sWv[CC*CC];
    const int t = threadIdx.x;
    for (int i = t; i < CQ*CC; i += 128) { sWq[i] = Wq[i]; sWk[i] = Wk[i]; }
    for (int i = t; i < CC*CC; i += 128) sWv[i] = Wv[i];
    __syncthreads();

    const int b = blockIdx.y;
    const int l = blockIdx.x * 128 + t;

    const float* xb = x + (size_t)b*CC*LL + l;
    float xr[CC];
#pragma unroll
    for (int c = 0; c < CC; c++) xr[c] = xb[(size_t)c*LL];

    float* qo = g_q + ((size_t)b*LL + l)*CQ;
#pragma unroll 4
    for (int o = 0; o < CQ; o++) {
        float a = bq[o];
        const float4* w = (const float4*)&sWq[o*CC];
#pragma unroll
        for (int c4 = 0; c4 < CC/4; c4++) {
            float4 w4 = w[c4];
            a += w4.x*xr[4*c4] + w4.y*xr[4*c4+1] + w4.z*xr[4*c4+2] + w4.w*xr[4*c4+3];
        }
        qo[o] = a;
    }
    float* ko = g_k + ((size_t)b*LL + l)*CQ;
#pragma unroll 4
    for (int o = 0; o < CQ; o++) {
        float a = bk[o];
        const float4* w = (const float4*)&sWk[o*CC];
#pragma unroll
        for (int c4 = 0; c4 < CC/4; c4++) {
            float4 w4 = w[c4];
            a += w4.x*xr[4*c4] + w4.y*xr[4*c4+1] + w4.z*xr[4*c4+2] + w4.w*xr[4*c4+3];
        }
        ko[o] = a;
    }
    float* vo = g_v + ((size_t)b*LL + l)*CC;
#pragma unroll 4
    for (int o = 0; o < CC; o++) {
        float a = bv[o];
        const float4* w = (const float4*)&sWv[o*CC];
#pragma unroll
        for (int c4 = 0; c4 < CC/4; c4++) {
            float4 w4 = w[c4];
            a += w4.x*xr[4*c4] + w4.y*xr[4*c4+1] + w4.z*xr[4*c4+2] + w4.w*xr[4*c4+3];
        }
        vo[o] = a;
    }
}

// ---------------- K2: stable counting sort of positions into buckets ----------------
__global__ void __launch_bounds__(256) k_bucket(const int* __restrict__ hash)
{
    const int h = blockIdx.x, b = blockIdx.y;
    const int* hb = hash + ((size_t)b*NH + h)*LL;
    const int t = threadIdx.x;

    __shared__ unsigned short cnt[256][NB]; // per-thread bucket counts -> prefix
    __shared__ int tot[NB];
    __shared__ int bstart[NB+1];

    for (int k = 0; k < NB; k++) cnt[t][k] = 0;
    __syncthreads();

    const int base = t * 16;
#pragma unroll
    for (int e = 0; e < 16; e++) {
        int bk = hb[base + e];
        cnt[t][bk]++;
    }
    __syncthreads();

    if (t < NB) {
        int s = 0;
        for (int r = 0; r < 256; r++) {
            unsigned short v = cnt[r][t];
            cnt[r][t] = (unsigned short)s;
            s += v;
        }
        tot[t] = s;
    }
    __syncthreads();
    if (t == 0) {
        int s = 0;
        for (int k = 0; k < NB; k++) { bstart[k] = s; s += tot[k]; }
        bstart[NB] = s;
    }
    __syncthreads();
    if (t < NB + 1) g_bstart[((size_t)b*NH + h)*(NB+1) + t] = bstart[t];

    int* out = g_sorted + ((size_t)b*NH + h)*LL;
#pragma unroll
    for (int e = 0; e < 16; e++) {
        int l = base + e;
        int bk = hb[l];
        int pos = bstart[bk] + cnt[t][bk];
        cnt[t][bk]++;
        out[pos] = l;
    }
}

// ---------------- K3: bucket-local softmax attention ----------------
__global__ void __launch_bounds__(128) k_attn()
{
    const int bucket = blockIdx.x, h = blockIdx.y, b = blockIdx.z;
    const int bh = b*NH + h;
    const int start = g_bstart[bh*(NB+1) + bucket];
    const int end   = g_bstart[bh*(NB+1) + bucket + 1];
    const int n = end - start;
    if (n <= 0) return;

    const int* __restrict__ sorted = g_sorted + (size_t)bh*LL + start;
    const float* __restrict__ kb = g_k + (size_t)b*LL*CQ;
    const float* __restrict__ vb = g_v + (size_t)b*LL*CC;
    const float* __restrict__ qb = g_q + (size_t)b*LL*CQ;
    float* __restrict__ ab = g_acc + (((size_t)h*BB + b)*LL)*CC;

    __shared__ __align__(16) float s_k[TJ*CQ];
    __shared__ __align__(16) float s_v[TJ*CC];

    const int tid = threadIdx.x;

    for (int q0 = 0; q0 < n; q0 += 128) {
        const int qi = q0 + tid;
        const bool act = qi < n;
        int gi = 0;
        float qr[CQ];
        if (act) {
            gi = sorted[qi];
            const float4* qs = (const float4*)(qb + (size_t)gi*CQ);
#pragma unroll
            for (int c4 = 0; c4 < CQ/4; c4++) {
                float4 v4 = qs[c4];
                qr[4*c4] = v4.x; qr[4*c4+1] = v4.y; qr[4*c4+2] = v4.z; qr[4*c4+3] = v4.w;
            }
        }

        // pass 1: row max
        float m = -3.0e38f;
        for (int j0 = 0; j0 < n; j0 += TJ) {
            const int tj = min(TJ, n - j0);
            __syncthreads();
            for (int t = tid; t < tj*CQ; t += 128) {
                int r = t >> 4, c = t & 15;
                s_k[t] = kb[(size_t)sorted[j0 + r]*CQ + c];
            }
            __syncthreads();
            if (act) {
                for (int j = 0; j < tj; j++) {
                    const float* kk = &s_k[j*CQ];
                    float s = 0.f;
#pragma unroll
                    for (int c = 0; c < CQ; c++) s += qr[c]*kk[c];
                    m = fmaxf(m, s);
                }
            }
        }

        // pass 2: exp + P@V + Z
        float acc[CC];
#pragma unroll
        for (int c = 0; c < CC; c++) acc[c] = 0.f;
        float Z = 0.f;

        for (int j0 = 0; j0 < n; j0 += TJ) {
            const int tj = min(TJ, n - j0);
            __syncthreads();
            for (int t = tid; t < tj*CQ; t += 128) {
                int r = t >> 4, c = t & 15;
                s_k[t] = kb[(size_t)sorted[j0 + r]*CQ + c];
            }
            for (int t = tid; t < tj*CC; t += 128) {
                int r = t >> 6, c = t & 63;
                s_v[t] = vb[(size_t)sorted[j0 + r]*CC + c];
            }
            __syncthreads();
            if (act) {
                for (int j = 0; j < tj; j++) {
                    const float* kk = &s_k[j*CQ];
                    float s = 0.f;
#pragma unroll
                    for (int c = 0; c < CQ; c++) s += qr[c]*kk[c];
                    float w = __expf(s - m);
                    Z += w;
                    const float4* vv = (const float4*)&s_v[j*CC];
#pragma unroll
                    for (int c4 = 0; c4 < CC/4; c4++) {
                        float4 v4 = vv[c4];
                        acc[4*c4]   += w*v4.x;
                        acc[4*c4+1] += w*v4.y;
                        acc[4*c4+2] += w*v4.z;
                        acc[4*c4+3] += w*v4.w;
                    }
                }
            }
        }

        if (act) {
            float inv = 1.0f / Z;
            float4* ap = (float4*)(ab + (size_t)gi*CC);
#pragma unroll
            for (int c4 = 0; c4 < CC/4; c4++) {
                float4 o;
                o.x = acc[4*c4]   * inv;
                o.y = acc[4*c4+1] * inv;
                o.z = acc[4*c4+2] * inv;
                o.w = acc[4*c4+3] * inv;
                ap[c4] = o;
            }
        }
    }
}

// ---------------- K4: output projection + gamma*out + x ----------------
__global__ void __launch_bounds__(128) k_proj(const float* __restrict__ x,
    const float* __restrict__ Wo, const float* __restrict__ bo,
    const float* __restrict__ gamma)
{
    __shared__ __align__(16) float sW[CC*CC];
    const int t = threadIdx.x;
    for (int i = t; i < CC*CC; i += 128) sW[i] = Wo[i];
    __syncthreads();

    const int b = blockIdx.y;
    const int l = blockIdx.x * 128 + t;

    float ar[CC];
    const float4* a0 = (const float4*)(g_acc + (((size_t)0*BB + b)*LL + l)*CC);
    const float4* a1 = (const float4*)(g_acc + (((size_t)1*BB + b)*LL + l)*CC);
    const float4* a2 = (const float4*)(g_acc + (((size_t)2*BB + b)*LL + l)*CC);
    const float4* a3 = (const float4*)(g_acc + (((size_t)3*BB + b)*LL + l)*CC);
#pragma unroll
    for (int c4 = 0; c4 < CC/4; c4++) {
        float4 s0 = a0[c4], s1 = a1[c4], s2 = a2[c4], s3 = a3[c4];
        ar[4*c4]   = (s0.x + s1.x + s2.x + s3.x) * 0.25f;
        ar[4*c4+1] = (s0.y + s1.y + s2.y + s3.y) * 0.25f;
        ar[4*c4+2] = (s0.z + s1.z + s2.z + s3.z) * 0.25f;
        ar[4*c4+3] = (s0.w + s1.w + s2.w + s3.w) * 0.25f;
    }

    const float g = gamma[0];
#pragma unroll 4
    for (int o = 0; o < CC; o++) {
        float s = bo[o];
        const float4* w = (const float4*)&sW[o*CC];
#pragma unroll
        for (int c4 = 0; c4 < CC/4; c4++) {
            float4 w4 = w[c4];
            s += w4.x*ar[4*c4] + w4.y*ar[4*c4+1] + w4.z*ar[4*c4+2] + w4.w*ar[4*c4+3];
        }
        size_t idx = ((size_t)b*CC + o)*LL + l;
        g_pre[idx] = g*s + x[idx];
    }
}

// ---------------- K5: per-channel sum/sumsq (deterministic) ----------------
__global__ void __launch_bounds__(256) k_stats()
{
    const int c = blockIdx.x;
    const int t = threadIdx.x;
    double s = 0.0, s2 = 0.0;
    for (int i = t; i < BB*LL; i += 256) {
        int b = i >> 12;
        int l = i & (LL - 1);
        float v = g_pre[((size_t)b*CC + c)*LL + l];
        s += (double)v;
        s2 += (double)v * (double)v;
    }
    __shared__ double rs[256], rs2[256];
    rs[t] = s; rs2[t] = s2;
    __syncthreads();
    for (int o = 128; o > 0; o >>= 1) {
        if (t < o) { rs[t] += rs[t+o]; rs2[t] += rs2[t+o]; }
        __syncthreads();
    }
    if (t == 0) {
        g_stats[c]      = (float)rs[0];
        g_stats[CC + c] = (float)rs2[0];
    }
}

// ---------------- K6: batchnorm finalize ----------------
__global__ void __launch_bounds__(256) k_norm(float* __restrict__ out,
    const float* __restrict__ bn_w, const float* __restrict__ bn_b)
{
    const int i = blockIdx.x * 256 + threadIdx.x;
    const int c = (i >> 12) & (CC - 1);
    const float invN = 1.0f / (float)(BB*LL);
    float mean = g_stats[c] * invN;
    float var  = g_stats[CC + c] * invN - mean*mean;
    out[i] = (g_pre[i] - mean) * rsqrtf(var + EPSV) * bn_w[c] + bn_b[c];
}

// ---------------- launch ----------------
extern "C" void kernel_launch(void* const* d_in, const int* in_sizes, int n_in,
                              void* d_out, int out_size)
{
    const float* x     = (const float*)d_in[0];
    const int*   hash  = (const int*)  d_in[1];
    const float* Wq    = (const float*)d_in[2];
    const float* bq    = (const float*)d_in[3];
    const float* Wk    = (const float*)d_in[4];
    const float* bk    = (const float*)d_in[5];
    const float* Wv    = (const float*)d_in[6];
    const float* bv    = (const float*)d_in[7];
    const float* Wo    = (const float*)d_in[8];
    const float* bo    = (const float*)d_in[9];
    const float* gamma = (const float*)d_in[10];
    const float* bnw   = (const float*)d_in[11];
    const float* bnb   = (const float*)d_in[12];
    float* out = (float*)d_out;

    k_qkv  <<<dim3(LL/128, BB), 128>>>(x, Wq, bq, Wk, bk, Wv, bv);
    k_bucket<<<dim3(NH, BB), 256>>>(hash);
    k_attn <<<dim3(NB, NH, BB), 128>>>();
    k_proj <<<dim3(LL/128, BB), 128>>>(x, Wo, bo, gamma);
    k_stats<<<CC, 256>>>();
    k_norm <<<(BB*CC*LL)/256, 256>>>(out, bnw, bnb);
}

// round 2
// speedup vs baseline: 1.3319x; 1.3319x over previous
#include <cuda_runtime.h>
#include <cuda_bf16.h>

#define BB 4
#define CC 64
#define LL 4096
#define CQ 16
#define NH 4
#define NB 32
#define TJ 128
#define EPSV 1e-5f
#define SHIFT 20.0f

// ---------------- scratch (device globals; no allocation at runtime) ----------------
__device__ float g_q[BB*LL*CQ];          // (b, l, cq)
__device__ float g_k[BB*LL*CQ];          // (b, l, cq)
__device__ float g_v[BB*LL*CC];          // (b, l, c)
__device__ int   g_sorted[BB*NH*LL];     // positions sorted by bucket (stable)
__device__ int   g_bstart[BB*NH*(NB+1)]; // bucket start offsets
__device__ float g_acc[NH*BB*LL*CC];     // per-hash attention output
__device__ float g_pre[BB*CC*LL];        // pre-batchnorm output
__device__ double g_part[CC*BB*2];       // per-(c,b) sum / sumsq partials

// ---------------- packed f32x2 helpers ----------------
__device__ __forceinline__ unsigned long long ffma2(unsigned long long a,
                                                    unsigned long long b,
                                                    unsigned long long c) {
    unsigned long long d;
    asm("fma.rn.f32x2 %0, %1, %2, %3;" : "=l"(d) : "l"(a), "l"(b), "l"(c));
    return d;
}
__device__ __forceinline__ unsigned long long pack2(float lo, float hi) {
    unsigned long long r;
    asm("mov.b64 %0, {%1, %2};" : "=l"(r)
        : "r"(__float_as_uint(lo)), "r"(__float_as_uint(hi)));
    return r;
}
__device__ __forceinline__ void unpack2(unsigned long long v, float& lo, float& hi) {
    unsigned int a, b;
    asm("mov.b64 {%0, %1}, %2;" : "=r"(a), "=r"(b) : "l"(v));
    lo = __uint_as_float(a); hi = __uint_as_float(b);
}

// ---------------- K1: q/k/v 1x1 convs, z-split for occupancy ----------------
// z = 0: q (16 ch), z = 1: k (16 ch), z = 2..5: v channels [16*(z-2), 16*(z-1))
__global__ void __launch_bounds__(128) k_qkv(const float* __restrict__ x,
    const float* __restrict__ Wq, const float* __restrict__ bq,
    const float* __restrict__ Wk, const float* __restrict__ bk,
    const float* __restrict__ Wv, const float* __restrict__ bv)
{
    __shared__ __align__(16) float sW[16*CC];
    __shared__ float sb[16];
    const int t = threadIdx.x;
    const int z = blockIdx.z;
    const int b = blockIdx.y;
    const int l = blockIdx.x * 128 + t;

    const float* W; const float* bias;
    if (z == 0)      { W = Wq; bias = bq; }
    else if (z == 1) { W = Wk; bias = bk; }
    else             { W = Wv + (z-2)*16*CC; bias = bv + (z-2)*16; }
    for (int i = t; i < 16*CC; i += 128) sW[i] = W[i];
    if (t < 16) sb[t] = bias[t];
    __syncthreads();

    const float* xb = x + (size_t)b*CC*LL + l;
    float xr[CC];
#pragma unroll
    for (int c = 0; c < CC; c++) xr[c] = xb[(size_t)c*LL];

    float out[16];
#pragma unroll 4
    for (int o = 0; o < 16; o++) {
        float a = sb[o];
        const float4* w = (const float4*)&sW[o*CC];
#pragma unroll
        for (int c4 = 0; c4 < CC/4; c4++) {
            float4 w4 = w[c4];
            a += w4.x*xr[4*c4] + w4.y*xr[4*c4+1] + w4.z*xr[4*c4+2] + w4.w*xr[4*c4+3];
        }
        out[o] = a;
    }

    float4* dst;
    if (z == 0)      dst = (float4*)(g_q + ((size_t)b*LL + l)*CQ);
    else if (z == 1) dst = (float4*)(g_k + ((size_t)b*LL + l)*CQ);
    else             dst = (float4*)(g_v + ((size_t)b*LL + l)*CC + (z-2)*16);
#pragma unroll
    for (int i = 0; i < 4; i++)
        dst[i] = make_float4(out[4*i], out[4*i+1], out[4*i+2], out[4*i+3]);
}

// ---------------- K2: stable counting sort of positions into buckets ----------------
__global__ void __launch_bounds__(256) k_bucket(const int* __restrict__ hash)
{
    const int h = blockIdx.x, b = blockIdx.y;
    const int* hb = hash + ((size_t)b*NH + h)*LL;
    const int t = threadIdx.x;

    __shared__ unsigned short cnt[256][NB];
    __shared__ int tot[NB];
    __shared__ int bstart[NB+1];

    for (int k = 0; k < NB; k++) cnt[t][k] = 0;
    __syncthreads();

    const int base = t * 16;
#pragma unroll
    for (int e = 0; e < 16; e++) cnt[t][hb[base + e]]++;
    __syncthreads();

    if (t < NB) {
        int s = 0;
        for (int r = 0; r < 256; r++) {
            unsigned short v = cnt[r][t];
            cnt[r][t] = (unsigned short)s;
            s += v;
        }
        tot[t] = s;
    }
    __syncthreads();
    if (t == 0) {
        int s = 0;
        for (int k = 0; k < NB; k++) { bstart[k] = s; s += tot[k]; }
        bstart[NB] = s;
    }
    __syncthreads();
    if (t < NB + 1) g_bstart[((size_t)b*NH + h)*(NB+1) + t] = bstart[t];

    int* out = g_sorted + ((size_t)b*NH + h)*LL;
#pragma unroll
    for (int e = 0; e < 16; e++) {
        int l = base + e;
        int bk = hb[l];
        out[bstart[bk] + cnt[t][bk]] = l;
        cnt[t][bk]++;
    }
}

// ---------------- K3: single-pass bucket softmax attention (no max pass) ----------------
__global__ void __launch_bounds__(128) k_attn()
{
    const int bucket = blockIdx.x, h = blockIdx.y, b = blockIdx.z;
    const int bh = b*NH + h;
    const int start = g_bstart[bh*(NB+1) + bucket];
    const int end   = g_bstart[bh*(NB+1) + bucket + 1];
    const int n = end - start;
    if (n <= 0) return;

    const int* __restrict__ sorted = g_sorted + (size_t)bh*LL + start;
    const float* __restrict__ kb = g_k + (size_t)b*LL*CQ;
    const float* __restrict__ vb = g_v + (size_t)b*LL*CC;
    const float* __restrict__ qb = g_q + (size_t)b*LL*CQ;
    float* __restrict__ ab = g_acc + (((size_t)h*BB + b)*LL)*CC;

    __shared__ __align__(16) float s_k[TJ*CQ];
    __shared__ __align__(16) float s_v[TJ*CC];

    const int tid = threadIdx.x;

    for (int q0 = 0; q0 < n; q0 += 128) {
        const int qi = q0 + tid;
        const bool act = qi < n;
        int gi = 0;
        unsigned long long q2[CQ/2];
        if (act) {
            gi = sorted[qi];
            const float4* qs = (const float4*)(qb + (size_t)gi*CQ);
#pragma unroll
            for (int c4 = 0; c4 < CQ/4; c4++) {
                float4 v4 = qs[c4];
                q2[2*c4]   = pack2(v4.x, v4.y);
                q2[2*c4+1] = pack2(v4.z, v4.w);
            }
        }

        unsigned long long acc2[CC/2];
#pragma unroll
        for (int c = 0; c < CC/2; c++) acc2[c] = 0ull;
        float Z = 0.f;

        for (int j0 = 0; j0 < n; j0 += TJ) {
            const int tj = min(TJ, n - j0);
            __syncthreads();
            // load k tile (float4 granularity)
            for (int t = tid; t < tj*(CQ/4); t += 128) {
                int r = t >> 2, c4 = t & 3;
                ((float4*)s_k)[t] = ((const float4*)(kb + (size_t)sorted[j0 + r]*CQ))[c4];
            }
            // load v tile
            for (int t = tid; t < tj*(CC/4); t += 128) {
                int r = t >> 4, c4 = t & 15;
                ((float4*)s_v)[(r*(CC/4)) + c4] = ((const float4*)(vb + (size_t)sorted[j0 + r]*CC))[c4];
            }
            __syncthreads();
            if (act) {
                for (int j = 0; j < tj; j++) {
                    const unsigned long long* kk2 = (const unsigned long long*)(s_k + j*CQ);
                    unsigned long long s2 = 0ull;
#pragma unroll
                    for (int c = 0; c < CQ/2; c++) s2 = ffma2(q2[c], kk2[c], s2);
                    float slo, shi; unpack2(s2, slo, shi);
                    float w = __expf(slo + shi - SHIFT);
                    Z += w;
                    unsigned long long w2 = pack2(w, w);
                    const unsigned long long* vv2 = (const unsigned long long*)(s_v + j*CC);
#pragma unroll
                    for (int c = 0; c < CC/2; c++) acc2[c] = ffma2(w2, vv2[c], acc2[c]);
                }
            }
        }

        if (act) {
            float inv = 1.0f / Z;
            float4* ap = (float4*)(ab + (size_t)gi*CC);
#pragma unroll
            for (int c4 = 0; c4 < CC/4; c4++) {
                float a0, a1, a2, a3;
                unpack2(acc2[2*c4],   a0, a1);
                unpack2(acc2[2*c4+1], a2, a3);
                ap[c4] = make_float4(a0*inv, a1*inv, a2*inv, a3*inv);
            }
        }
    }
}

// ---------------- K4: output projection + residual (shared-tile) ----------------
__global__ void __launch_bounds__(256) k_proj(const float* __restrict__ x,
    const float* __restrict__ Wo, const float* __restrict__ bo,
    const float* __restrict__ gamma)
{
    __shared__ __align__(16) float sA[64*65];   // 64 tokens x 64 ch (padded)
    __shared__ __align__(16) float sW[CC*CC];
    const int t = threadIdx.x;
    const int b = blockIdx.y;
    const int l0 = blockIdx.x * 64;

    for (int i = t; i < CC*CC; i += 256) sW[i] = Wo[i];
    // stage acc tile, averaged over hashes (coalesced: c fast)
    {
        const size_t base = ((size_t)b*LL + l0)*CC;
        for (int i = t; i < 64*CC; i += 256) {
            int tok = i >> 6, c = i & 63;
            float s = g_acc[((size_t)0*BB*LL*CC) + base + i]
                    + g_acc[((size_t)1*BB*LL*CC) + base + i]
                    + g_acc[((size_t)2*BB*LL*CC) + base + i]
                    + g_acc[((size_t)3*BB*LL*CC) + base + i];
            sA[tok*65 + c] = s * 0.25f;
        }
    }
    __syncthreads();

    const int w  = t >> 5;   // warp 0..7 -> channels w*8 .. w*8+7
    const int ln = t & 31;   // token lane
    const float g = gamma[0];

    float accA[8], accB[8];
#pragma unroll
    for (int k = 0; k < 8; k++) { accA[k] = bo[w*8 + k]; accB[k] = accA[k]; }

#pragma unroll 4
    for (int cin = 0; cin < CC; cin++) {
        float a1 = sA[ln*65 + cin];
        float a2 = sA[(ln+32)*65 + cin];
#pragma unroll
        for (int k = 0; k < 8; k++) {
            float wv = sW[(w*8 + k)*CC + cin];
            accA[k] += wv * a1;
            accB[k] += wv * a2;
        }
    }

#pragma unroll
    for (int k = 0; k < 8; k++) {
        int c = w*8 + k;
        size_t i1 = ((size_t)b*CC + c)*LL + l0 + ln;
        size_t i2 = i1 + 32;
        g_pre[i1] = g*accA[k] + x[i1];
        g_pre[i2] = g*accB[k] + x[i2];
    }
}

// ---------------- K5: per-(channel,batch) sum/sumsq partials (deterministic) ----------------
__global__ void __launch_bounds__(256) k_stats()
{
    const int c = blockIdx.x, b = blockIdx.y, t = threadIdx.x;
    const float* p = g_pre + ((size_t)b*CC + c)*LL;
    double s = 0.0, s2 = 0.0;
    for (int l = t; l < LL; l += 256) {
        float v = p[l];
        s += (double)v;
        s2 += (double)v * (double)v;
    }
    __shared__ double rs[256], rs2[256];
    rs[t] = s; rs2[t] = s2;
    __syncthreads();
    for (int o = 128; o > 0; o >>= 1) {
        if (t < o) { rs[t] += rs[t+o]; rs2[t] += rs2[t+o]; }
        __syncthreads();
    }
    if (t == 0) {
        g_part[(c*BB + b)*2]     = rs[0];
        g_part[(c*BB + b)*2 + 1] = rs2[0];
    }
}

// ---------------- K6: batchnorm finalize (fused partial combine) ----------------
__global__ void __launch_bounds__(256) k_norm(float* __restrict__ out,
    const float* __restrict__ bn_w, const float* __restrict__ bn_b)
{
    __shared__ float s_scale, s_shift;
    const int i = blockIdx.x * 256 + threadIdx.x;
    const int c = (i >> 12) & (CC - 1);
    if (threadIdx.x == 0) {
        double s = 0.0, s2 = 0.0;
        for (int b = 0; b < BB; b++) {
            s  += g_part[(c*BB + b)*2];
            s2 += g_part[(c*BB + b)*2 + 1];
        }
        double mean = s * (1.0/(BB*LL));
        double var  = s2 * (1.0/(BB*LL)) - mean*mean;
        float rstd = rsqrtf((float)var + EPSV);
        float sc = rstd * bn_w[c];
        s_scale = sc;
        s_shift = bn_b[c] - (float)mean * sc;
    }
    __syncthreads();
    out[i] = g_pre[i] * s_scale + s_shift;
}

// ---------------- launch ----------------
extern "C" void kernel_launch(void* const* d_in, const int* in_sizes, int n_in,
                              void* d_out, int out_size)
{
    const float* x     = (const float*)d_in[0];
    const int*   hash  = (const int*)  d_in[1];
    const float* Wq    = (const float*)d_in[2];
    const float* bq    = (const float*)d_in[3];
    const float* Wk    = (const float*)d_in[4];
    const float* bk    = (const float*)d_in[5];
    const float* Wv    = (const float*)d_in[6];
    const float* bv    = (const float*)d_in[7];
    const float* Wo    = (const float*)d_in[8];
    const float* bo    = (const float*)d_in[9];
    const float* gamma = (const float*)d_in[10];
    const float* bnw   = (const float*)d_in[11];
    const float* bnb   = (const float*)d_in[12];
    float* out = (float*)d_out;

    k_qkv  <<<dim3(LL/128, BB, 6), 128>>>(x, Wq, bq, Wk, bk, Wv, bv);
    k_bucket<<<dim3(NH, BB), 256>>>(hash);
    k_attn <<<dim3(NB, NH, BB), 128>>>();
    k_proj <<<dim3(LL/64, BB), 256>>>(x, Wo, bo, gamma);
    k_stats<<<dim3(CC, BB), 256>>>();
    k_norm <<<(BB*CC*LL)/256, 256>>>(out, bnw, bnb);
}

// round 3
// speedup vs baseline: 1.4497x; 1.0884x over previous
#include <cuda_runtime.h>
#include <cuda_fp16.h>
#include <cuda_bf16.h>

#define BB 4
#define CC 64
#define LL 4096
#define CQ 16
#define NH 4
#define NB 32
#define TJ 128
#define EPSV 1e-5f
#define SHIFT 20.0f
#define NPB (BB*(LL/64))   // 256 proj blocks -> stat partials

// ---------------- scratch (device globals; no allocation at runtime) ----------------
__device__ float g_q[BB*LL*CQ];
__device__ float g_k[BB*LL*CQ];
__device__ float g_v[BB*LL*CC];
__device__ int   g_sorted[BB*NH*LL];
__device__ int   g_bstart[BB*NH*(NB+1)];
__device__ __align__(16) __half g_acch[NH*BB*LL*CC];   // fp16 per-hash attention output (8MB)
__device__ float g_pre[BB*CC*LL];
__device__ float g_psum[CC*NPB];
__device__ float g_psq[CC*NPB];
__device__ float g_ss[2*CC];                            // per-channel scale/shift

// ---------------- packed f32x2 helpers ----------------
__device__ __forceinline__ unsigned long long ffma2(unsigned long long a,
                                                    unsigned long long b,
                                                    unsigned long long c) {
    unsigned long long d;
    asm("fma.rn.f32x2 %0, %1, %2, %3;" : "=l"(d) : "l"(a), "l"(b), "l"(c));
    return d;
}
__device__ __forceinline__ unsigned long long pack2(float lo, float hi) {
    unsigned long long r;
    asm("mov.b64 %0, {%1, %2};" : "=l"(r)
        : "r"(__float_as_uint(lo)), "r"(__float_as_uint(hi)));
    return r;
}
__device__ __forceinline__ void unpack2(unsigned long long v, float& lo, float& hi) {
    unsigned int a, b;
    asm("mov.b64 {%0, %1}, %2;" : "=r"(a), "=r"(b) : "l"(v));
    lo = __uint_as_float(a); hi = __uint_as_float(b);
}

// ---------------- K1: q/k/v 1x1 convs, z-split ----------------
__global__ void __launch_bounds__(128) k_qkv(const float* __restrict__ x,
    const float* __restrict__ Wq, const float* __restrict__ bq,
    const float* __restrict__ Wk, const float* __restrict__ bk,
    const float* __restrict__ Wv, const float* __restrict__ bv)
{
    __shared__ __align__(16) float sW[16*CC];
    __shared__ float sb[16];
    const int t = threadIdx.x;
    const int z = blockIdx.z;
    const int b = blockIdx.y;
    const int l = blockIdx.x * 128 + t;

    const float* W; const float* bias;
    if (z == 0)      { W = Wq; bias = bq; }
    else if (z == 1) { W = Wk; bias = bk; }
    else             { W = Wv + (z-2)*16*CC; bias = bv + (z-2)*16; }
    for (int i = t; i < 16*CC; i += 128) sW[i] = W[i];
    if (t < 16) sb[t] = bias[t];
    __syncthreads();

    const float* xb = x + (size_t)b*CC*LL + l;
    float xr[CC];
#pragma unroll
    for (int c = 0; c < CC; c++) xr[c] = xb[(size_t)c*LL];

    float out[16];
#pragma unroll 4
    for (int o = 0; o < 16; o++) {
        float a = sb[o];
        const float4* w = (const float4*)&sW[o*CC];
#pragma unroll
        for (int c4 = 0; c4 < CC/4; c4++) {
            float4 w4 = w[c4];
            a += w4.x*xr[4*c4] + w4.y*xr[4*c4+1] + w4.z*xr[4*c4+2] + w4.w*xr[4*c4+3];
        }
        out[o] = a;
    }

    float4* dst;
    if (z == 0)      dst = (float4*)(g_q + ((size_t)b*LL + l)*CQ);
    else if (z == 1) dst = (float4*)(g_k + ((size_t)b*LL + l)*CQ);
    else             dst = (float4*)(g_v + ((size_t)b*LL + l)*CC + (z-2)*16);
#pragma unroll
    for (int i = 0; i < 4; i++)
        dst[i] = make_float4(out[4*i], out[4*i+1], out[4*i+2], out[4*i+3]);
}

// ---------------- K2: stable counting sort ----------------
__global__ void __launch_bounds__(256) k_bucket(const int* __restrict__ hash)
{
    const int h = blockIdx.x, b = blockIdx.y;
    const int* hb = hash + ((size_t)b*NH + h)*LL;
    const int t = threadIdx.x;

    __shared__ unsigned short cnt[256][NB];
    __shared__ int tot[NB];
    __shared__ int bstart[NB+1];

    for (int k = 0; k < NB; k++) cnt[t][k] = 0;
    __syncthreads();

    const int base = t * 16;
#pragma unroll
    for (int e = 0; e < 16; e++) cnt[t][hb[base + e]]++;
    __syncthreads();

    if (t < NB) {
        int s = 0;
        for (int r = 0; r < 256; r++) {
            unsigned short v = cnt[r][t];
            cnt[r][t] = (unsigned short)s;
            s += v;
        }
        tot[t] = s;
    }
    __syncthreads();
    if (t == 0) {
        int s = 0;
        for (int k = 0; k < NB; k++) { bstart[k] = s; s += tot[k]; }
        bstart[NB] = s;
    }
    __syncthreads();
    if (t < NB + 1) g_bstart[((size_t)b*NH + h)*(NB+1) + t] = bstart[t];

    int* out = g_sorted + ((size_t)b*NH + h)*LL;
#pragma unroll
    for (int e = 0; e < 16; e++) {
        int l = base + e;
        int bk = hb[l];
        out[bstart[bk] + cnt[t][bk]] = l;
        cnt[t][bk]++;
    }
}

// ---------------- K3: single-pass bucket softmax attention ----------------
__global__ void __launch_bounds__(128) k_attn()
{
    const int bucket = blockIdx.x, h = blockIdx.y, b = blockIdx.z;
    const int bh = b*NH + h;
    const int start = g_bstart[bh*(NB+1) + bucket];
    const int end   = g_bstart[bh*(NB+1) + bucket + 1];
    const int n = end - start;
    if (n <= 0) return;

    const int* __restrict__ sorted = g_sorted + (size_t)bh*LL + start;
    const float* __restrict__ kb = g_k + (size_t)b*LL*CQ;
    const float* __restrict__ vb = g_v + (size_t)b*LL*CC;
    const float* __restrict__ qb = g_q + (size_t)b*LL*CQ;
    __half* __restrict__ ab = g_acch + (((size_t)h*BB + b)*LL)*CC;

    __shared__ __align__(16) float s_k[TJ*CQ];
    __shared__ __align__(16) float s_v[TJ*CC];

    const int tid = threadIdx.x;

    for (int q0 = 0; q0 < n; q0 += 128) {
        const int qi = q0 + tid;
        const bool act = qi < n;
        int gi = 0;
        unsigned long long q2[CQ/2];
        if (act) {
            gi = sorted[qi];
            const float4* qs = (const float4*)(qb + (size_t)gi*CQ);
#pragma unroll
            for (int c4 = 0; c4 < CQ/4; c4++) {
                float4 v4 = qs[c4];
                q2[2*c4]   = pack2(v4.x, v4.y);
                q2[2*c4+1] = pack2(v4.z, v4.w);
            }
        }

        unsigned long long acc2[CC/2];
#pragma unroll
        for (int c = 0; c < CC/2; c++) acc2[c] = 0ull;
        float Z = 0.f;

        for (int j0 = 0; j0 < n; j0 += TJ) {
            const int tj = min(TJ, n - j0);
            __syncthreads();
            for (int t = tid; t < tj*(CQ/4); t += 128) {
                int r = t >> 2, c4 = t & 3;
                ((float4*)s_k)[t] = ((const float4*)(kb + (size_t)sorted[j0 + r]*CQ))[c4];
            }
            for (int t = tid; t < tj*(CC/4); t += 128) {
                int r = t >> 4, c4 = t & 15;
                ((float4*)s_v)[(r*(CC/4)) + c4] = ((const float4*)(vb + (size_t)sorted[j0 + r]*CC))[c4];
            }
            __syncthreads();
            if (act) {
                for (int j = 0; j < tj; j++) {
                    const ulonglong2* kk = (const ulonglong2*)(s_k + j*CQ);
                    unsigned long long s2 = 0ull;
#pragma unroll
                    for (int c = 0; c < CQ/4; c++) {
                        ulonglong2 kp = kk[c];
                        s2 = ffma2(q2[2*c],   kp.x, s2);
                        s2 = ffma2(q2[2*c+1], kp.y, s2);
                    }
                    float slo, shi; unpack2(s2, slo, shi);
                    float w = __expf(slo + shi - SHIFT);
                    Z += w;
                    unsigned long long w2 = pack2(w, w);
                    const ulonglong2* vv = (const ulonglong2*)(s_v + j*CC);
#pragma unroll
                    for (int c = 0; c < CC/4; c++) {
                        ulonglong2 vp = vv[c];
                        acc2[2*c]   = ffma2(w2, vp.x, acc2[2*c]);
                        acc2[2*c+1] = ffma2(w2, vp.y, acc2[2*c+1]);
                    }
                }
            }
        }

        if (act) {
            float inv = 1.0f / Z;
            unsigned int hw[CC/2];
#pragma unroll
            for (int c = 0; c < CC/2; c++) {
                float a0, a1; unpack2(acc2[c], a0, a1);
                __half2 h2 = __floats2half2_rn(a0*inv, a1*inv);
                hw[c] = *(unsigned int*)&h2;
            }
            uint4* ap = (uint4*)(ab + (size_t)gi*CC);
#pragma unroll
            for (int g = 0; g < CC/8; g++)
                ap[g] = make_uint4(hw[4*g], hw[4*g+1], hw[4*g+2], hw[4*g+3]);
        }
    }
}

// ---------------- K4: projection + residual + fused per-block stats ----------------
__global__ void __launch_bounds__(256) k_proj(const float* __restrict__ x,
    const float* __restrict__ Wo, const float* __restrict__ bo,
    const float* __restrict__ gamma)
{
    __shared__ __align__(16) float sA[64*65];
    __shared__ __align__(16) float sW[CC*CC];
    const int t = threadIdx.x;
    const int b = blockIdx.y;
    const int l0 = blockIdx.x * 64;

    for (int i = t; i < CC*CC; i += 256) sW[i] = Wo[i];
    {
        const size_t base2 = (((size_t)b*LL + l0)*CC) >> 1;       // half2 index
        const size_t plane = ((size_t)BB*LL*CC) >> 1;
        const __half2* A = (const __half2*)g_acch;
        for (int i = t; i < 64*(CC/2); i += 256) {
            float2 f0 = __half22float2(A[0*plane + base2 + i]);
            float2 f1 = __half22float2(A[1*plane + base2 + i]);
            float2 f2 = __half22float2(A[2*plane + base2 + i]);
            float2 f3 = __half22float2(A[3*plane + base2 + i]);
            int tok = i >> 5, c2 = i & 31;
            sA[tok*65 + 2*c2]     = (f0.x + f1.x + f2.x + f3.x) * 0.25f;
            sA[tok*65 + 2*c2 + 1] = (f0.y + f1.y + f2.y + f3.y) * 0.25f;
        }
    }
    __syncthreads();

    const int w  = t >> 5;   // warp -> channels w*8..w*8+7
    const int ln = t & 31;   // token lane
    const float g = gamma[0];

    float accA[8], accB[8];
#pragma unroll
    for (int k = 0; k < 8; k++) { accA[k] = bo[w*8 + k]; accB[k] = accA[k]; }

#pragma unroll 4
    for (int cin = 0; cin < CC; cin++) {
        float a1 = sA[ln*65 + cin];
        float a2 = sA[(ln+32)*65 + cin];
#pragma unroll
        for (int k = 0; k < 8; k++) {
            float wv = sW[(w*8 + k)*CC + cin];
            accA[k] += wv * a1;
            accB[k] += wv * a2;
        }
    }

    const int blk = b*(LL/64) + blockIdx.x;
#pragma unroll
    for (int k = 0; k < 8; k++) {
        int c = w*8 + k;
        size_t i1 = ((size_t)b*CC + c)*LL + l0 + ln;
        size_t i2 = i1 + 32;
        float o1 = g*accA[k] + x[i1];
        float o2 = g*accB[k] + x[i2];
        g_pre[i1] = o1;
        g_pre[i2] = o2;
        float s  = o1 + o2;
        float sq = o1*o1 + o2*o2;
#pragma unroll
        for (int off = 16; off > 0; off >>= 1) {
            s  += __shfl_down_sync(0xffffffffu, s,  off);
            sq += __shfl_down_sync(0xffffffffu, sq, off);
        }
        if (ln == 0) {
            g_psum[c*NPB + blk] = s;
            g_psq [c*NPB + blk] = sq;
        }
    }
}

// ---------------- K5: finalize per-channel scale/shift ----------------
__global__ void __launch_bounds__(256) k_finstat(const float* __restrict__ bn_w,
                                                 const float* __restrict__ bn_b)
{
    const int c = blockIdx.x, t = threadIdx.x;
    __shared__ double rs[256], rs2[256];
    rs[t]  = (double)g_psum[c*NPB + t];
    rs2[t] = (double)g_psq [c*NPB + t];
    __syncthreads();
    for (int o = 128; o > 0; o >>= 1) {
        if (t < o) { rs[t] += rs[t+o]; rs2[t] += rs2[t+o]; }
        __syncthreads();
    }
    if (t == 0) {
        double mean = rs[0] * (1.0/(BB*LL));
        double var  = rs2[0] * (1.0/(BB*LL)) - mean*mean;
        float rstd = rsqrtf((float)var + EPSV);
        float sc = rstd * bn_w[c];
        g_ss[2*c]   = sc;
        g_ss[2*c+1] = bn_b[c] - (float)mean * sc;
    }
}

// ---------------- K6: batchnorm apply (vectorized) ----------------
__global__ void __launch_bounds__(256) k_norm(float* __restrict__ out)
{
    const int i4 = blockIdx.x * 256 + threadIdx.x;
    const int c = (i4 >> 10) & (CC - 1);          // 1024 float4 per (b,c) row
    const float sc = g_ss[2*c], sh = g_ss[2*c+1];
    float4 p = ((const float4*)g_pre)[i4];
    ((float4*)out)[i4] = make_float4(p.x*sc + sh, p.y*sc + sh, p.z*sc + sh, p.w*sc + sh);
}

// ---------------- launch ----------------
extern "C" void kernel_launch(void* const* d_in, const int* in_sizes, int n_in,
                              void* d_out, int out_size)
{
    const float* x     = (const float*)d_in[0];
    const int*   hash  = (const int*)  d_in[1];
    const float* Wq    = (const float*)d_in[2];
    const float* bq    = (const float*)d_in[3];
    const float* Wk    = (const float*)d_in[4];
    const float* bk    = (const float*)d_in[5];
    const float* Wv    = (const float*)d_in[6];
    const float* bv    = (const float*)d_in[7];
    const float* Wo    = (const float*)d_in[8];
    const float* bo    = (const float*)d_in[9];
    const float* gamma = (const float*)d_in[10];
    const float* bnw   = (const float*)d_in[11];
    const float* bnb   = (const float*)d_in[12];
    float* out = (float*)d_out;

    k_qkv   <<<dim3(LL/128, BB, 6), 128>>>(x, Wq, bq, Wk, bk, Wv, bv);
    k_bucket<<<dim3(NH, BB), 256>>>(hash);
    k_attn  <<<dim3(NB, NH, BB), 128>>>();
    k_proj  <<<dim3(LL/64, BB), 256>>>(x, Wo, bo, gamma);
    k_finstat<<<CC, 256>>>(bnw, bnb);
    k_norm  <<<(BB*CC*LL)/(4*256), 256>>>(out);
}